// round 4
// baseline (speedup 1.0000x reference)
#include <cuda_runtime.h>
#include <cuda_bf16.h>
#include <cstdint>

// Embedding gather + sinusoidal positional encoding.
// out[row, c] = W[ids[row], c] + (row even ? sin : cos)(row * freq(c)),
//   freq(c) = 10000^(-2c/D)
//
// D = 1024, TOKENS = 8192.
// Block = 4 rows x 1024 cols, 256 threads; thread t owns columns 4t..4t+3.
// All 4 gather loads front-batched; ids loaded directly (uniform LDG, no smem
// round-trip). PE via rotor recurrence seeded by accurate sincosf.
// __launch_bounds__(256, 5) caps regs to lift occupancy (was 64 regs / 4 CTAs).

static constexpr int D       = 1024;
static constexpr int VEC     = 4;
static constexpr int THREADS = D / VEC;   // 256
static constexpr int R       = 4;         // rows per block (even!)

__global__ __launch_bounds__(THREADS, 5)
void emb_pe_kernel(const int* __restrict__ ids,
                   const float* __restrict__ W,
                   float* __restrict__ out)
{
    const int row0 = blockIdx.x * R;          // always even
    const int t    = threadIdx.x;             // 0..255
    const int c0   = t * VEC;                 // starting column

    // Uniform ids loads: one 16B sector, broadcast across the warp.
    int id[R];
#pragma unroll
    for (int r = 0; r < R; r++)
        id[r] = __ldg(ids + row0 + r);

    const float* Wc = W + c0;

    // Front-batch all row gathers (4 independent LDG.128 in flight).
    float4 v[R];
#pragma unroll
    for (int r = 0; r < R; r++)
        v[r] = *reinterpret_cast<const float4*>(Wc + (size_t)id[r] * D);

    // freq(c) = 2^(kexp * c),  kexp = -2*log2(10000)/D  (overlaps load latency)
    const float kexp = -13.287712379549449f * 2.0f / (float)D;
    const float pos0 = (float)row0;

    float s[VEC], c[VEC], sd[VEC], cd[VEC];
#pragma unroll
    for (int i = 0; i < VEC; i++) {
        float freq = exp2f(kexp * (float)(c0 + i));
        sincosf(pos0 * freq, &s[i], &c[i]);   // start rotor (accurate)
        sincosf(freq,        &sd[i], &cd[i]); // per-row delta rotor
    }

    float* outp = out + (size_t)row0 * D + c0;

#pragma unroll
    for (int r = 0; r < R; r += 2) {
        // even row: add sin
        float4 o0;
        o0.x = v[r].x + s[0];
        o0.y = v[r].y + s[1];
        o0.z = v[r].z + s[2];
        o0.w = v[r].w + s[3];
        *reinterpret_cast<float4*>(outp + (size_t)r * D) = o0;

        // rotate to row r+1
#pragma unroll
        for (int i = 0; i < VEC; i++) {
            float ns = fmaf(s[i], cd[i],  c[i] * sd[i]);
            float nc = fmaf(c[i], cd[i], -s[i] * sd[i]);
            s[i] = ns; c[i] = nc;
        }

        // odd row: add cos
        float4 o1;
        o1.x = v[r + 1].x + c[0];
        o1.y = v[r + 1].y + c[1];
        o1.z = v[r + 1].z + c[2];
        o1.w = v[r + 1].w + c[3];
        *reinterpret_cast<float4*>(outp + (size_t)(r + 1) * D) = o1;

        // rotate to row r+2 (dead on the last iteration; compiler drops it)
#pragma unroll
        for (int i = 0; i < VEC; i++) {
            float ns = fmaf(s[i], cd[i],  c[i] * sd[i]);
            float nc = fmaf(c[i], cd[i], -s[i] * sd[i]);
            s[i] = ns; c[i] = nc;
        }
    }
}

extern "C" void kernel_launch(void* const* d_in, const int* in_sizes, int n_in,
                              void* d_out, int out_size)
{
    const int*   ids = (const int*)d_in[0];
    const float* W   = (const float*)d_in[1];
    float*       out = (float*)d_out;

    const int rows = in_sizes[0];             // 8192 tokens
    emb_pe_kernel<<<rows / R, THREADS>>>(ids, W, out);
}